// round 15
// baseline (speedup 1.0000x reference)
#include <cuda_runtime.h>

#define BATCH  32
#define NBOX   8732
#define DDIM   93
#define NCLS   80
#define KC     512
#define PC     1024            // pending buffer capacity
#define CAP    2048            // fast-path candidate buffer capacity
#define NMSMAX 400
#define TOPK   200
#define FLAT   (NCLS*NMSMAX)   // 32000 (= 125*256)
#define FLAT4  (FLAT & ~1023)  // 31744 = 31*1024 (4-way main loop bound)
#define CONF_T 0.01f
#define IOU_T  0.45f
#define NBIN   4096
#define MTRI   4352             // triangular bitmap words: sum_i (16 - (i>>5))
#define PREF   0.875f           // prefilter (exact bin boundary 0x3F600000)
#define C_HI   0.45000450f      // conservative band: > uni*C_HI  => IOU > 0.45 surely
#define C_LO   0.44999550f      // < uni*C_LO => IOU <= 0.45 surely; between: exact fdiv
#define TKSLICE 8               // pass-A slices per batch

typedef unsigned long long u64;
typedef unsigned int u32;

#define SK(i) ((i) + ((i) >> 5))   // skewed smem index (bank-conflict relief)

// Barrier before a bitonic layer of stride j (prev layer stride 2j).
// Warp w owns elements [64w,64w+64) for strides <=32. Need __syncthreads iff j >= 32.
#define LAYER_BAR(j) do { if ((j) >= 32) __syncthreads(); else __syncwarp(); } while (0)

// triangular row base: row i stores words [i>>5, 16) at M[RB(i) + w - (i>>5)]
__device__ __forceinline__ int RB(int i) {
    int k = i >> 5;
    return 16*i - k*(i - 16*k - 16);
}

// fine monotone bucket over (0.875, 1]: 4096 bins of 2^9 float-bit steps; clamped
__device__ __forceinline__ int BKT(u32 sb) {
    int v = (int)(sb - 0x3F600000u) >> 9;
    return v < 0 ? 0 : (v > (NBIN-1) ? (NBIN-1) : v);
}

// ---------------- static scratch (no allocations allowed) ----------------
__device__ float4 g_boxes[BATCH*NBOX];
__device__ float  g_scoresT[(size_t)BATCH*NCLS*NBOX];
__device__ u64    g_cands[(size_t)BATCH*NCLS*KC];
__device__ __align__(16) float g_flat[(size_t)BATCH*FLAT*6];
__device__ __align__(16) float g_topscore[(size_t)BATCH*FLAT];
__device__ u32    g_hist[BATCH*NBIN];          // 512 KB, zeroed in k_decode

// ---------------- kernel 1: decode boxes + transpose scores (+ zero g_hist) ----------------
#define TILE_N 64
__global__ void k_decode(const float* __restrict__ y) {
    __shared__ float t[TILE_N*DDIM];
    int b  = blockIdx.y;
    int n0 = blockIdx.x * TILE_N;
    // zero g_hist: first 512 linear blocks clear 256 words each (BATCH*NBIN = 131072)
    {
        int linear = blockIdx.y * gridDim.x + blockIdx.x;
        if (linear < (BATCH*NBIN)/256)
            g_hist[linear*256 + threadIdx.x] = 0u;
    }
    int nn = min(TILE_N, NBOX - n0);
    const float* src = y + ((size_t)b*NBOX + n0)*DDIM;
    for (int i = threadIdx.x; i < nn*DDIM; i += blockDim.x) t[i] = src[i];
    __syncthreads();

    if (threadIdx.x < nn) {
        const float* r = t + threadIdx.x*DDIM;
        float aw = r[87], ah = r[88];
        float cx = __fadd_rn(__fmul_rn(__fmul_rn(r[81], r[89]), aw), r[85]);
        float cy = __fadd_rn(__fmul_rn(__fmul_rn(r[82], r[90]), ah), r[86]);
        float w  = __fmul_rn(expf(__fmul_rn(r[83], r[91])), aw);
        float h  = __fmul_rn(expf(__fmul_rn(r[84], r[92])), ah);
        float xmin = __fmul_rn(__fsub_rn(cx, __fmul_rn(0.5f, w)), 512.0f);
        float ymin = __fmul_rn(__fsub_rn(cy, __fmul_rn(0.5f, h)), 512.0f);
        float xmax = __fmul_rn(__fadd_rn(cx, __fmul_rn(0.5f, w)), 512.0f);
        float ymax = __fmul_rn(__fadd_rn(cy, __fmul_rn(0.5f, h)), 512.0f);
        g_boxes[(size_t)b*NBOX + n0 + threadIdx.x] = make_float4(xmin, ymin, xmax, ymax);
    }
    for (int idx = threadIdx.x; idx < NCLS*TILE_N; idx += blockDim.x) {
        int c = idx / TILE_N, i = idx % TILE_N;
        if (i < nn)
            g_scoresT[((size_t)(b*NCLS + c))*NBOX + n0 + i] = t[i*DDIM + 1 + c];
    }
}

// ---------------- kernel 2: top-512 (round-12/13 passing version, unchanged) ----------------
__global__ void k_select() {
    __shared__ u64 cur[KC + KC/32];     // 528  (fallback accumulator)
    __shared__ u64 pend[PC + PC/32];    // 1056
    __shared__ u64 buf[CAP + CAP/32];   // 2112
    __shared__ u32 hist[NBIN];          // 16 KB
    __shared__ int s_pcnt, s_admit, s_bcnt;
    __shared__ u64 s_hthr;
    int task = blockIdx.x;
    int t = threadIdx.x;                // 0..255
    int lane = t & 31;
    const float* sc = g_scoresT + (size_t)task*NBOX;

    cur[SK(t)] = 0ULL; cur[SK(t+256)] = 0ULL;
    #pragma unroll
    for (int r = 0; r < 4; ++r) pend[SK(t + r*256)] = 0ULL;
    #pragma unroll
    for (int r = 0; r < NBIN/256; ++r) hist[t + r*256] = 0u;
    if (t == 0) { s_pcnt = 0; s_hthr = 0ULL; s_admit = 0x7FFFFFFF; s_bcnt = 0; }
    __syncthreads();

    // ---- single-read compaction of keys with s > PREF ----
    for (int nb = 0; nb < NBOX; nb += 256) {
        int n = nb + t;
        u64 key = 0ULL; bool pass = false;
        if (n < NBOX) {
            float s = sc[n];
            if (s > PREF) {
                key = ((u64)__float_as_uint(s) << 32) | (u64)(0xFFFFFFFFu - (u32)n);
                pass = true;
            }
        }
        u32 m = __ballot_sync(0xFFFFFFFFu, pass);
        int rank = __popc(m & ((1u << lane) - 1u));
        u32 posb = 0;
        if (lane == 0 && m) posb = atomicAdd(&s_bcnt, __popc(m));
        posb = __shfl_sync(0xFFFFFFFFu, posb, 0);
        if (pass) {
            u32 pos = posb + rank;
            if (pos < CAP) buf[SK(pos)] = key;
        }
    }
    __syncthreads();
    int bcnt = s_bcnt;
    bool fast = (bcnt >= KC && bcnt <= CAP);

    if (fast) {
        for (int i = t; i < bcnt; i += 256)
            atomicAdd(&hist[(u32)(buf[SK(i)] >> 51)], 1u);
    } else {
        for (int n = t; n < NBOX; n += 256) {
            float s = sc[n];
            if (s > PREF) atomicAdd(&hist[__float_as_uint(s) >> 19], 1u);
        }
    }
    __syncthreads();
    if (t < 32) {
        int cum = 0;
        for (int c = NBIN/32 - 1; c >= 0; --c) {
            u32 h = hist[c*32 + lane];
            if (!__ballot_sync(0xFFFFFFFFu, h != 0u)) continue;
            u32 sfx = h;
            #pragma unroll
            for (int off = 1; off < 32; off <<= 1) {
                u32 v = __shfl_down_sync(0xFFFFFFFFu, sfx, off);
                if (lane + off < 32) sfx += v;
            }
            u32 tot = __shfl_sync(0xFFFFFFFFu, sfx, 0);
            if (cum + (int)tot >= KC) {
                bool cond = (cum + (int)sfx) >= KC;
                u32 mask = __ballot_sync(0xFFFFFFFFu, cond);
                int L = 31 - __clz(mask);
                u32 B = (u32)(c*32 + L);
                u32 adm = cum + __shfl_sync(0xFFFFFFFFu, sfx, L);
                if (lane == 0) { s_hthr = ((u64)(B << 19)) << 32; s_admit = (int)adm; }
                break;
            }
            cum += (int)tot;
        }
    }
    __syncthreads();
    u64 hthr = s_hthr;
    int admit = s_admit;

    if (fast && admit <= PC) {
        for (int nb = 0; nb < CAP; nb += 256) {
            int i = nb + t;
            u64 key = 0ULL; bool pass = false;
            if (i < bcnt) { key = buf[SK(i)]; pass = key > hthr; }
            u32 m = __ballot_sync(0xFFFFFFFFu, pass);
            int rank = __popc(m & ((1u << lane) - 1u));
            u32 posb = 0;
            if (lane == 0 && m) posb = atomicAdd(&s_pcnt, __popc(m));
            posb = __shfl_sync(0xFFFFFFFFu, posb, 0);
            if (pass) pend[SK(posb + rank)] = key;
        }
        __syncthreads();
        for (int kk = 2; kk <= PC; kk <<= 1) {
            for (int j = kk >> 1; j > 0; j >>= 1) {
                LAYER_BAR(j);
                #pragma unroll
                for (int r = 0; r < 2; ++r) {
                    int pi = t + r*256;
                    int i = ((pi & ~(j-1)) << 1) | (pi & (j-1));
                    int q = i | j;
                    bool up = ((i & kk) == 0);
                    u64 a = pend[SK(i)], bb = pend[SK(q)];
                    if (up ? (a < bb) : (a > bb)) { pend[SK(i)] = bb; pend[SK(q)] = a; }
                }
            }
        }
        __syncthreads();
        g_cands[(size_t)task*KC + t]       = pend[SK(t)];
        g_cands[(size_t)task*KC + t + 256] = pend[SK(t + 256)];
        return;
    }

    // ---- fallback: chunked filtered compaction (exact for any input) ----
    const int nch = (NBOX + KC - 1)/KC;
    for (int cidx = 0; cidx < nch; ++cidx) {
        u64 thr0 = cur[SK(KC-1)];
        u64 thr = (thr0 > hthr) ? thr0 : hthr;
        int base = cidx*KC;
        #pragma unroll
        for (int r = 0; r < 2; ++r) {
            int n = base + t + r*256;
            u64 key = 0ULL;
            if (n < NBOX) {
                float s = sc[n];
                if (s > CONF_T)
                    key = ((u64)__float_as_uint(s) << 32) | (u64)(0xFFFFFFFFu - (u32)n);
            }
            bool pass = key > thr;
            u32 mask = __ballot_sync(0xFFFFFFFFu, pass);
            int rank = __popc(mask & ((1u << lane) - 1u));
            u32 posb = 0;
            if (lane == 0 && mask) posb = atomicAdd(&s_pcnt, __popc(mask));
            posb = __shfl_sync(0xFFFFFFFFu, posb, 0);
            if (pass) {
                u32 pos = posb + rank;
                if (pos < PC) pend[SK(pos)] = key;
            }
        }
        __syncthreads();
        int p = s_pcnt;
        __syncthreads();
        bool last = (cidx == nch - 1);
        bool fl = (admit <= PC) ? (last && p > 0)
                                : ((p > KC) || (last && p > 0));
        if (fl) {
            for (int kk = 2; kk <= PC; kk <<= 1) {
                for (int j = kk >> 1; j > 0; j >>= 1) {
                    LAYER_BAR(j);
                    #pragma unroll
                    for (int r = 0; r < 2; ++r) {
                        int pi = t + r*256;
                        int i = ((pi & ~(j-1)) << 1) | (pi & (j-1));
                        int q = i | j;
                        bool up = ((i & kk) == 0);
                        u64 a = pend[SK(i)], bb = pend[SK(q)];
                        if (up ? (a > bb) : (a < bb)) { pend[SK(i)] = bb; pend[SK(q)] = a; }
                    }
                }
            }
            __syncthreads();
            {
                u64 a = cur[SK(t)],      bb = pend[SK(KC + t)];
                cur[SK(t)] = (a > bb) ? a : bb;
                u64 a2 = cur[SK(t+256)], b2 = pend[SK(KC + t + 256)];
                cur[SK(t+256)] = (a2 > b2) ? a2 : b2;
            }
            for (int j = KC >> 1; j > 0; j >>= 1) {
                LAYER_BAR(j);
                int i = ((t & ~(j-1)) << 1) | (t & (j-1));
                int q = i | j;
                u64 a = cur[SK(i)], bb = cur[SK(q)];
                if (a < bb) { cur[SK(i)] = bb; cur[SK(q)] = a; }
            }
            __syncthreads();
            #pragma unroll
            for (int r = 0; r < 4; ++r) pend[SK(t + r*256)] = 0ULL;
            if (t == 0) s_pcnt = 0;
            __syncthreads();
        }
    }
    g_cands[(size_t)task*KC + t]       = cur[SK(t)];
    g_cands[(size_t)task*KC + t + 256] = cur[SK(t + 256)];
}

// ---------------- kernel 3: bit-matrix greedy NMS (measured-best config) ----------------
__global__ void k_nms() {
    __shared__ float4 B4[KC];            // 8 KB
    __shared__ float AR[KC], SC[KC];     // 4 KB
    __shared__ u32 M[MTRI];              // 17408 B
    __shared__ short KP[NMSMAX];
    __shared__ int s_nv, s_kept;
    int task = blockIdx.x;
    int b = task / NCLS, c = task % NCLS;
    int t = threadIdx.x, lane = t & 31;

    if (t == 0) s_nv = KC;
    #pragma unroll
    for (int r = 0; r < MTRI/256; ++r) M[t + r*256] = 0u;
    __syncthreads();

    const u64* cand = g_cands + (size_t)task*KC;
    #pragma unroll
    for (int r = 0; r < 2; ++r) {
        int i = t + r*256;
        u64 key = cand[i];
        u32 hi = (u32)(key >> 32);
        float4 bx = make_float4(0.f,0.f,0.f,0.f);
        if (hi != 0u) {
            bx = g_boxes[(size_t)b*NBOX + (0xFFFFFFFFu - (u32)key)];
        } else {
            atomicMin(&s_nv, i);
        }
        B4[i] = bx;
        AR[i] = __fmul_rn(__fsub_rn(bx.z,bx.x), __fsub_rn(bx.w,bx.y));
        SC[i] = __uint_as_float(hi);
    }
    __syncthreads();
    int nv = s_nv;

    #pragma unroll
    for (int rr = 0; rr < 2; ++rr) {
        int i = rr ? (KC-1-t) : t;
        if (i < nv - 1) {
            float4 bi = B4[i];
            float ia = AR[i];
            int k = i >> 5;
            int base = RB(i) - k;
            int wend = (nv + 31) >> 5;
            for (int w = (i+1) >> 5; w < wend; ++w) {
                u32 bits = 0u;
                int j0 = max(i+1, w << 5);
                int j1 = min(nv, (w+1) << 5);
                for (int j = j0; j < j1; ++j) {
                    float4 bj = B4[j];
                    float xx1 = fmaxf(bi.x, bj.x);
                    float yy1 = fmaxf(bi.y, bj.y);
                    float xx2 = fminf(bi.z, bj.z);
                    float yy2 = fminf(bi.w, bj.w);
                    float dw = fmaxf(__fsub_rn(xx2, xx1), 0.0f);
                    float dh = fmaxf(__fsub_rn(yy2, yy1), 0.0f);
                    float inter = __fmul_rn(dw, dh);
                    float uni = __fsub_rn(__fadd_rn(ia, AR[j]), inter);
                    bool hit;
                    if      (inter > __fmul_rn(uni, C_HI)) hit = (uni > 0.0f);
                    else if (inter < __fmul_rn(uni, C_LO)) hit = false;
                    else hit = (uni > 0.0f) && (__fdiv_rn(inter, uni) > IOU_T);
                    bits |= ((u32)hit) << (j & 31);
                }
                M[base + w] = bits;
            }
        }
    }
    __syncthreads();

    if (t < 32) {                        // serial greedy, warp 0; rem in registers
        u32 myrem;
        {
            int lo = lane*32;
            if      (lane >= 16)     myrem = 0xFFFFFFFFu;
            else if (nv >= lo + 32)  myrem = 0u;
            else if (nv <= lo)       myrem = 0xFFFFFFFFu;
            else                     myrem = ~((1u << (nv - lo)) - 1u);
        }
        int kept = 0;
        for (int i = 0; i < nv; ++i) {
            int k = i >> 5;
            u32 wv = __shfl_sync(0xFFFFFFFFu, myrem, k);
            if (!((wv >> (i & 31)) & 1u)) {
                if (lane == 0) KP[kept] = (short)i;
                kept++;
                if (kept >= NMSMAX) break;
                if (lane >= k && lane < 16)
                    myrem |= M[RB(i) - k + lane];
            }
        }
        if (lane == 0) s_kept = kept;
    }
    __syncthreads();
    int kept = s_kept;
    for (int p = t; p < NMSMAX; p += 256) {      // full block: entries + zero tail
        size_t o = (size_t)b*FLAT + c*NMSMAX + p;
        float* e = g_flat + o*6;
        if (p < kept) {
            int j = KP[p];
            float4 bx = B4[j];
            g_topscore[o] = SC[j];
            e[0] = (float)(c+1);
            e[1] = SC[j];
            e[2] = bx.x; e[3] = bx.y; e[4] = bx.z; e[5] = bx.w;
        } else {
            g_topscore[o] = 0.0f;
            e[0]=0.f; e[1]=0.f; e[2]=0.f; e[3]=0.f; e[4]=0.f; e[5]=0.f;
        }
    }
}

// ---------------- kernel 4a: per-batch fine histogram, 8 slices/batch ----------------
__global__ void k_topk_a() {
    __shared__ u32 hist[NBIN];
    int sl = blockIdx.x, b = blockIdx.y, t = threadIdx.x;
    #pragma unroll
    for (int r = 0; r < NBIN/256; ++r) hist[t + r*256] = 0u;
    __syncthreads();
    const float* sc = g_topscore + (size_t)b*FLAT;
    const int per = FLAT / TKSLICE;                 // 4000
    int i0 = sl * per;
    for (int i = i0 + t; i < i0 + per; i += 256) {
        float s = sc[i];
        if (s > 0.0f) atomicAdd(&hist[BKT(__float_as_uint(s))], 1u);
    }
    __syncthreads();
    #pragma unroll
    for (int r = 0; r < NBIN/256; ++r) {
        u32 h = hist[t + r*256];
        if (h) atomicAdd(&g_hist[b*NBIN + t + r*256], h);
    }
}

// ---------------- kernel 4b: pivot + compact + single 512-sort ----------------
// Pivot bucket B1 = fine bucket of the rank-200 score; admit whole bucket
// (tie-exact: intra-bucket order resolved by the full-key sort). Fallback to the
// exact full-scan chunked path if pivot not found (n < 200) or adm > 512.
__global__ void k_topk(float* __restrict__ out) {
    __shared__ u32 hist[NBIN];          // 16 KB
    __shared__ u64 pend[KC + KC/32];    // 4.2 KB
    __shared__ u64 cur[256];
    __shared__ u64 chk[KC];
    __shared__ int s_b1, s_adm, s_pcnt;
    int b = blockIdx.x, t = threadIdx.x, lane = t & 31;
    if (t == 0) { s_b1 = -1; s_adm = 0x7FFFFFFF; s_pcnt = 0; }
    #pragma unroll
    for (int r = 0; r < NBIN/256; ++r) hist[t + r*256] = g_hist[b*NBIN + t + r*256];
    __syncthreads();

    const float* sc = g_topscore + (size_t)b*FLAT;

    if (t < 32) {                       // pivot: rank TOPK from the top
        int cum = 0;
        for (int c = NBIN/32 - 1; c >= 0; --c) {
            u32 h = hist[c*32 + lane];
            if (!__ballot_sync(0xFFFFFFFFu, h != 0u)) continue;
            u32 sfx = h;
            #pragma unroll
            for (int off = 1; off < 32; off <<= 1) {
                u32 v = __shfl_down_sync(0xFFFFFFFFu, sfx, off);
                if (lane + off < 32) sfx += v;
            }
            u32 tot = __shfl_sync(0xFFFFFFFFu, sfx, 0);
            if (cum + (int)tot >= TOPK) {
                bool cond = (cum + (int)sfx) >= TOPK;
                u32 mask = __ballot_sync(0xFFFFFFFFu, cond);
                int L = 31 - __clz(mask);
                u32 sfxL = __shfl_sync(0xFFFFFFFFu, sfx, L);
                if (lane == 0) { s_b1 = c*32 + L; s_adm = cum + (int)sfxL; }
                break;
            }
            cum += (int)tot;
        }
    }
    __syncthreads();
    int B1 = s_b1, adm = s_adm;

    if (B1 >= 0 && adm <= KC) {
        pend[SK(t)] = 0ULL; pend[SK(t+256)] = 0ULL;
        __syncthreads();
        // 4-way pipelined scan over FLAT4 (31*1024), then one exact 256-wide tail
        for (int nb = 0; nb < FLAT4; nb += 1024) {
            float sv[4];
            #pragma unroll
            for (int r = 0; r < 4; ++r) sv[r] = sc[nb + r*256 + t];
            #pragma unroll
            for (int r = 0; r < 4; ++r) {
                int i = nb + r*256 + t;
                float s = sv[r];
                bool pass = (s > 0.0f) && (BKT(__float_as_uint(s)) >= B1);
                u64 key = ((u64)__float_as_uint(s) << 32) | (u64)(0xFFFFFFFFu - (u32)i);
                u32 m = __ballot_sync(0xFFFFFFFFu, pass);
                if (m) {
                    int rank = __popc(m & ((1u << lane) - 1u));
                    u32 posb = 0;
                    if (lane == 0) posb = atomicAdd(&s_pcnt, __popc(m));
                    posb = __shfl_sync(0xFFFFFFFFu, posb, 0);
                    if (pass) pend[SK(posb + rank)] = key;   // <= adm <= 512
                }
            }
        }
        {   // tail: FLAT - FLAT4 = 256 elements exactly
            int i = FLAT4 + t;
            float s = sc[i];
            bool pass = (s > 0.0f) && (BKT(__float_as_uint(s)) >= B1);
            u64 key = ((u64)__float_as_uint(s) << 32) | (u64)(0xFFFFFFFFu - (u32)i);
            u32 m = __ballot_sync(0xFFFFFFFFu, pass);
            if (m) {
                int rank = __popc(m & ((1u << lane) - 1u));
                u32 posb = 0;
                if (lane == 0) posb = atomicAdd(&s_pcnt, __popc(m));
                posb = __shfl_sync(0xFFFFFFFFu, posb, 0);
                if (pass) pend[SK(posb + rank)] = key;
            }
        }
        __syncthreads();
        for (int kk = 2; kk <= KC; kk <<= 1) {
            for (int j = kk >> 1; j > 0; j >>= 1) {
                LAYER_BAR(j);
                int i = ((t & ~(j-1)) << 1) | (t & (j-1));
                int q = i | j;
                bool up = ((i & kk) == 0);
                u64 a = pend[SK(i)], bb = pend[SK(q)];
                if (up ? (a < bb) : (a > bb)) { pend[SK(i)] = bb; pend[SK(q)] = a; }
            }
        }
        __syncthreads();
        for (int idx = t; idx < TOPK*6; idx += 256) {
            int k = idx / 6, r = idx % 6;
            u64 key = pend[SK(k)];
            u32 flat = 0xFFFFFFFFu - (u32)key;
            out[((size_t)b*TOPK + k)*6 + r] = g_flat[((size_t)b*FLAT + flat)*6 + r];
        }
        return;
    }

    // ---- fallback: exact chunked selection over all FLAT slots ----
    cur[t] = 0ULL;
    __syncthreads();
    int nchc = (FLAT + KC - 1)/KC;
    for (int cidx = 0; cidx < nchc; ++cidx) {
        int base = cidx*KC;
        #pragma unroll
        for (int r = 0; r < 2; ++r) {
            int i = t + r*256;
            int g = base + i;
            u64 key = 0ULL;
            if (g < FLAT) {
                float s = sc[g];
                key = ((u64)__float_as_uint(s) << 32) | (u64)(0xFFFFFFFFu - (u32)g);
            }
            chk[i] = key;
        }
        __syncthreads();
        for (int kk = 2; kk <= KC; kk <<= 1) {
            for (int j = kk >> 1; j > 0; j >>= 1) {
                LAYER_BAR(j);
                int i = ((t & ~(j-1)) << 1) | (t & (j-1));
                int p = i | j;
                bool up = ((i & kk) == 0);
                u64 a = chk[i], bb = chk[p];
                if (up ? (a > bb) : (a < bb)) { chk[i] = bb; chk[p] = a; }
            }
        }
        __syncthreads();
        {
            u64 a = cur[t], bb = chk[256 + t];
            cur[t] = (a > bb) ? a : bb;
        }
        for (int j = 128; j > 0; j >>= 1) {
            LAYER_BAR(j);
            if (t < 128) {
                int i = ((t & ~(j-1)) << 1) | (t & (j-1));
                int p = i | j;
                u64 a = cur[i], bb = cur[p];
                if (a < bb) { cur[i] = bb; cur[p] = a; }
            }
        }
        __syncthreads();
    }
    for (int idx = t; idx < TOPK*6; idx += 256) {
        int k = idx / 6, r = idx % 6;
        u64 key = cur[k];
        u32 flat = 0xFFFFFFFFu - (u32)key;
        out[((size_t)b*TOPK + k)*6 + r] = g_flat[((size_t)b*FLAT + flat)*6 + r];
    }
}

// ---------------- launcher ----------------
extern "C" void kernel_launch(void* const* d_in, const int* in_sizes, int n_in,
                              void* d_out, int out_size) {
    const float* y = (const float*)d_in[0];
    float* out = (float*)d_out;

    k_decode<<<dim3((NBOX + TILE_N - 1)/TILE_N, BATCH), 256>>>(y);
    k_select<<<BATCH*NCLS, 256>>>();
    k_nms<<<BATCH*NCLS, 256>>>();
    k_topk_a<<<dim3(TKSLICE, BATCH), 256>>>();
    k_topk<<<BATCH, 256>>>(out);
}

// round 16
// speedup vs baseline: 1.5644x; 1.5644x over previous
#include <cuda_runtime.h>

#define BATCH  32
#define NBOX   8732
#define DDIM   93
#define NCLS   80
#define KC     512
#define PC     1024            // pending buffer capacity
#define CAP    2048            // fast-path candidate buffer capacity
#define NMSMAX 400
#define TOPK   200
#define FLAT   (NCLS*NMSMAX)   // 32000 (= 125*256)
#define FLAT4  (FLAT & ~1023)  // 31744 = 31*1024 (4-way main loop bound)
#define CONF_T 0.01f
#define IOU_T  0.45f
#define NBIN   4096
#define MTRI   4352             // triangular bitmap words: sum_i (16 - (i>>5))
#define PREF   0.875f           // prefilter (exact bin boundary 0x3F600000)
#define C_HI   0.45000450f      // conservative band: > uni*C_HI  => IOU > 0.45 surely
#define C_LO   0.44999550f      // < uni*C_LO => IOU <= 0.45 surely; between: exact fdiv

typedef unsigned long long u64;
typedef unsigned int u32;

#define SK(i) ((i) + ((i) >> 5))   // skewed smem index (bank-conflict relief)

// Barrier before a bitonic layer of stride j (prev layer stride 2j).
// Warp w owns elements [64w,64w+64) for strides <=32. Need __syncthreads iff j >= 32.
#define LAYER_BAR(j) do { if ((j) >= 32) __syncthreads(); else __syncwarp(); } while (0)

// triangular row base: row i stores words [i>>5, 16) at M[RB(i) + w - (i>>5)]
__device__ __forceinline__ int RB(int i) {
    int k = i >> 5;
    return 16*i - k*(i - 16*k - 16);
}

// fine monotone bucket over (0.875, 1]: 4096 bins of 2^9 float-bit steps; clamped
__device__ __forceinline__ int BKT(u32 sb) {
    int v = (int)(sb - 0x3F600000u) >> 9;
    return v < 0 ? 0 : (v > (NBIN-1) ? (NBIN-1) : v);
}

// ---------------- static scratch (no allocations allowed) ----------------
__device__ float4 g_boxes[BATCH*NBOX];
__device__ float  g_scoresT[(size_t)BATCH*NCLS*NBOX];
__device__ u64    g_cands[(size_t)BATCH*NCLS*KC];
__device__ __align__(16) float g_flat[(size_t)BATCH*FLAT*6];
__device__ __align__(16) float g_topscore[(size_t)BATCH*FLAT];
__device__ u32    g_hist[BATCH*NBIN];          // 512 KB, zeroed in k_decode

// ---------------- kernel 1: decode boxes + transpose scores (+ zero g_hist) ----------------
#define TILE_N 64
__global__ void k_decode(const float* __restrict__ y) {
    __shared__ float t[TILE_N*DDIM];
    int b  = blockIdx.y;
    int n0 = blockIdx.x * TILE_N;
    // zero g_hist: first 512 linear blocks clear 256 words each (BATCH*NBIN = 131072)
    {
        int linear = blockIdx.y * gridDim.x + blockIdx.x;
        if (linear < (BATCH*NBIN)/256)
            g_hist[linear*256 + threadIdx.x] = 0u;
    }
    int nn = min(TILE_N, NBOX - n0);
    const float* src = y + ((size_t)b*NBOX + n0)*DDIM;
    for (int i = threadIdx.x; i < nn*DDIM; i += blockDim.x) t[i] = src[i];
    __syncthreads();

    if (threadIdx.x < nn) {
        const float* r = t + threadIdx.x*DDIM;
        float aw = r[87], ah = r[88];
        float cx = __fadd_rn(__fmul_rn(__fmul_rn(r[81], r[89]), aw), r[85]);
        float cy = __fadd_rn(__fmul_rn(__fmul_rn(r[82], r[90]), ah), r[86]);
        float w  = __fmul_rn(expf(__fmul_rn(r[83], r[91])), aw);
        float h  = __fmul_rn(expf(__fmul_rn(r[84], r[92])), ah);
        float xmin = __fmul_rn(__fsub_rn(cx, __fmul_rn(0.5f, w)), 512.0f);
        float ymin = __fmul_rn(__fsub_rn(cy, __fmul_rn(0.5f, h)), 512.0f);
        float xmax = __fmul_rn(__fadd_rn(cx, __fmul_rn(0.5f, w)), 512.0f);
        float ymax = __fmul_rn(__fadd_rn(cy, __fmul_rn(0.5f, h)), 512.0f);
        g_boxes[(size_t)b*NBOX + n0 + threadIdx.x] = make_float4(xmin, ymin, xmax, ymax);
    }
    for (int idx = threadIdx.x; idx < NCLS*TILE_N; idx += blockDim.x) {
        int c = idx / TILE_N, i = idx % TILE_N;
        if (i < nn)
            g_scoresT[((size_t)(b*NCLS + c))*NBOX + n0 + i] = t[i*DDIM + 1 + c];
    }
}

// ---------------- kernel 2: top-512 (round-12/13 passing version, unchanged) ----------------
__global__ void k_select() {
    __shared__ u64 cur[KC + KC/32];     // 528  (fallback accumulator)
    __shared__ u64 pend[PC + PC/32];    // 1056
    __shared__ u64 buf[CAP + CAP/32];   // 2112
    __shared__ u32 hist[NBIN];          // 16 KB
    __shared__ int s_pcnt, s_admit, s_bcnt;
    __shared__ u64 s_hthr;
    int task = blockIdx.x;
    int t = threadIdx.x;                // 0..255
    int lane = t & 31;
    const float* sc = g_scoresT + (size_t)task*NBOX;

    cur[SK(t)] = 0ULL; cur[SK(t+256)] = 0ULL;
    #pragma unroll
    for (int r = 0; r < 4; ++r) pend[SK(t + r*256)] = 0ULL;
    #pragma unroll
    for (int r = 0; r < NBIN/256; ++r) hist[t + r*256] = 0u;
    if (t == 0) { s_pcnt = 0; s_hthr = 0ULL; s_admit = 0x7FFFFFFF; s_bcnt = 0; }
    __syncthreads();

    // ---- single-read compaction of keys with s > PREF ----
    for (int nb = 0; nb < NBOX; nb += 256) {
        int n = nb + t;
        u64 key = 0ULL; bool pass = false;
        if (n < NBOX) {
            float s = sc[n];
            if (s > PREF) {
                key = ((u64)__float_as_uint(s) << 32) | (u64)(0xFFFFFFFFu - (u32)n);
                pass = true;
            }
        }
        u32 m = __ballot_sync(0xFFFFFFFFu, pass);
        int rank = __popc(m & ((1u << lane) - 1u));
        u32 posb = 0;
        if (lane == 0 && m) posb = atomicAdd(&s_bcnt, __popc(m));
        posb = __shfl_sync(0xFFFFFFFFu, posb, 0);
        if (pass) {
            u32 pos = posb + rank;
            if (pos < CAP) buf[SK(pos)] = key;
        }
    }
    __syncthreads();
    int bcnt = s_bcnt;
    bool fast = (bcnt >= KC && bcnt <= CAP);

    if (fast) {
        for (int i = t; i < bcnt; i += 256)
            atomicAdd(&hist[(u32)(buf[SK(i)] >> 51)], 1u);
    } else {
        for (int n = t; n < NBOX; n += 256) {
            float s = sc[n];
            if (s > PREF) atomicAdd(&hist[__float_as_uint(s) >> 19], 1u);
        }
    }
    __syncthreads();
    if (t < 32) {
        int cum = 0;
        for (int c = NBIN/32 - 1; c >= 0; --c) {
            u32 h = hist[c*32 + lane];
            if (!__ballot_sync(0xFFFFFFFFu, h != 0u)) continue;
            u32 sfx = h;
            #pragma unroll
            for (int off = 1; off < 32; off <<= 1) {
                u32 v = __shfl_down_sync(0xFFFFFFFFu, sfx, off);
                if (lane + off < 32) sfx += v;
            }
            u32 tot = __shfl_sync(0xFFFFFFFFu, sfx, 0);
            if (cum + (int)tot >= KC) {
                bool cond = (cum + (int)sfx) >= KC;
                u32 mask = __ballot_sync(0xFFFFFFFFu, cond);
                int L = 31 - __clz(mask);
                u32 B = (u32)(c*32 + L);
                u32 adm = cum + __shfl_sync(0xFFFFFFFFu, sfx, L);
                if (lane == 0) { s_hthr = ((u64)(B << 19)) << 32; s_admit = (int)adm; }
                break;
            }
            cum += (int)tot;
        }
    }
    __syncthreads();
    u64 hthr = s_hthr;
    int admit = s_admit;

    if (fast && admit <= PC) {
        for (int nb = 0; nb < CAP; nb += 256) {
            int i = nb + t;
            u64 key = 0ULL; bool pass = false;
            if (i < bcnt) { key = buf[SK(i)]; pass = key > hthr; }
            u32 m = __ballot_sync(0xFFFFFFFFu, pass);
            int rank = __popc(m & ((1u << lane) - 1u));
            u32 posb = 0;
            if (lane == 0 && m) posb = atomicAdd(&s_pcnt, __popc(m));
            posb = __shfl_sync(0xFFFFFFFFu, posb, 0);
            if (pass) pend[SK(posb + rank)] = key;
        }
        __syncthreads();
        for (int kk = 2; kk <= PC; kk <<= 1) {
            for (int j = kk >> 1; j > 0; j >>= 1) {
                LAYER_BAR(j);
                #pragma unroll
                for (int r = 0; r < 2; ++r) {
                    int pi = t + r*256;
                    int i = ((pi & ~(j-1)) << 1) | (pi & (j-1));
                    int q = i | j;
                    bool up = ((i & kk) == 0);
                    u64 a = pend[SK(i)], bb = pend[SK(q)];
                    if (up ? (a < bb) : (a > bb)) { pend[SK(i)] = bb; pend[SK(q)] = a; }
                }
            }
        }
        __syncthreads();
        g_cands[(size_t)task*KC + t]       = pend[SK(t)];
        g_cands[(size_t)task*KC + t + 256] = pend[SK(t + 256)];
        return;
    }

    // ---- fallback: chunked filtered compaction (exact for any input) ----
    const int nch = (NBOX + KC - 1)/KC;
    for (int cidx = 0; cidx < nch; ++cidx) {
        u64 thr0 = cur[SK(KC-1)];
        u64 thr = (thr0 > hthr) ? thr0 : hthr;
        int base = cidx*KC;
        #pragma unroll
        for (int r = 0; r < 2; ++r) {
            int n = base + t + r*256;
            u64 key = 0ULL;
            if (n < NBOX) {
                float s = sc[n];
                if (s > CONF_T)
                    key = ((u64)__float_as_uint(s) << 32) | (u64)(0xFFFFFFFFu - (u32)n);
            }
            bool pass = key > thr;
            u32 mask = __ballot_sync(0xFFFFFFFFu, pass);
            int rank = __popc(mask & ((1u << lane) - 1u));
            u32 posb = 0;
            if (lane == 0 && mask) posb = atomicAdd(&s_pcnt, __popc(mask));
            posb = __shfl_sync(0xFFFFFFFFu, posb, 0);
            if (pass) {
                u32 pos = posb + rank;
                if (pos < PC) pend[SK(pos)] = key;
            }
        }
        __syncthreads();
        int p = s_pcnt;
        __syncthreads();
        bool last = (cidx == nch - 1);
        bool fl = (admit <= PC) ? (last && p > 0)
                                : ((p > KC) || (last && p > 0));
        if (fl) {
            for (int kk = 2; kk <= PC; kk <<= 1) {
                for (int j = kk >> 1; j > 0; j >>= 1) {
                    LAYER_BAR(j);
                    #pragma unroll
                    for (int r = 0; r < 2; ++r) {
                        int pi = t + r*256;
                        int i = ((pi & ~(j-1)) << 1) | (pi & (j-1));
                        int q = i | j;
                        bool up = ((i & kk) == 0);
                        u64 a = pend[SK(i)], bb = pend[SK(q)];
                        if (up ? (a > bb) : (a < bb)) { pend[SK(i)] = bb; pend[SK(q)] = a; }
                    }
                }
            }
            __syncthreads();
            {
                u64 a = cur[SK(t)],      bb = pend[SK(KC + t)];
                cur[SK(t)] = (a > bb) ? a : bb;
                u64 a2 = cur[SK(t+256)], b2 = pend[SK(KC + t + 256)];
                cur[SK(t+256)] = (a2 > b2) ? a2 : b2;
            }
            for (int j = KC >> 1; j > 0; j >>= 1) {
                LAYER_BAR(j);
                int i = ((t & ~(j-1)) << 1) | (t & (j-1));
                int q = i | j;
                u64 a = cur[SK(i)], bb = cur[SK(q)];
                if (a < bb) { cur[SK(i)] = bb; cur[SK(q)] = a; }
            }
            __syncthreads();
            #pragma unroll
            for (int r = 0; r < 4; ++r) pend[SK(t + r*256)] = 0ULL;
            if (t == 0) s_pcnt = 0;
            __syncthreads();
        }
    }
    g_cands[(size_t)task*KC + t]       = cur[SK(t)];
    g_cands[(size_t)task*KC + t + 256] = cur[SK(t + 256)];
}

// ---------------- kernel 3: bit-matrix greedy NMS (measured-best config) ----------------
// Epilogue: writes kept rows + zero tail AND accumulates the per-batch fine
// score histogram directly (replaces the separate k_topk_a pass).
__global__ void k_nms() {
    __shared__ float4 B4[KC];            // 8 KB
    __shared__ float AR[KC], SC[KC];     // 4 KB
    __shared__ u32 M[MTRI];              // 17408 B
    __shared__ short KP[NMSMAX];
    __shared__ int s_nv, s_kept;
    int task = blockIdx.x;
    int b = task / NCLS, c = task % NCLS;
    int t = threadIdx.x, lane = t & 31;

    if (t == 0) s_nv = KC;
    #pragma unroll
    for (int r = 0; r < MTRI/256; ++r) M[t + r*256] = 0u;
    __syncthreads();

    const u64* cand = g_cands + (size_t)task*KC;
    #pragma unroll
    for (int r = 0; r < 2; ++r) {
        int i = t + r*256;
        u64 key = cand[i];
        u32 hi = (u32)(key >> 32);
        float4 bx = make_float4(0.f,0.f,0.f,0.f);
        if (hi != 0u) {
            bx = g_boxes[(size_t)b*NBOX + (0xFFFFFFFFu - (u32)key)];
        } else {
            atomicMin(&s_nv, i);
        }
        B4[i] = bx;
        AR[i] = __fmul_rn(__fsub_rn(bx.z,bx.x), __fsub_rn(bx.w,bx.y));
        SC[i] = __uint_as_float(hi);
    }
    __syncthreads();
    int nv = s_nv;

    #pragma unroll
    for (int rr = 0; rr < 2; ++rr) {
        int i = rr ? (KC-1-t) : t;
        if (i < nv - 1) {
            float4 bi = B4[i];
            float ia = AR[i];
            int k = i >> 5;
            int base = RB(i) - k;
            int wend = (nv + 31) >> 5;
            for (int w = (i+1) >> 5; w < wend; ++w) {
                u32 bits = 0u;
                int j0 = max(i+1, w << 5);
                int j1 = min(nv, (w+1) << 5);
                for (int j = j0; j < j1; ++j) {
                    float4 bj = B4[j];
                    float xx1 = fmaxf(bi.x, bj.x);
                    float yy1 = fmaxf(bi.y, bj.y);
                    float xx2 = fminf(bi.z, bj.z);
                    float yy2 = fminf(bi.w, bj.w);
                    float dw = fmaxf(__fsub_rn(xx2, xx1), 0.0f);
                    float dh = fmaxf(__fsub_rn(yy2, yy1), 0.0f);
                    float inter = __fmul_rn(dw, dh);
                    float uni = __fsub_rn(__fadd_rn(ia, AR[j]), inter);
                    bool hit;
                    if      (inter > __fmul_rn(uni, C_HI)) hit = (uni > 0.0f);
                    else if (inter < __fmul_rn(uni, C_LO)) hit = false;
                    else hit = (uni > 0.0f) && (__fdiv_rn(inter, uni) > IOU_T);
                    bits |= ((u32)hit) << (j & 31);
                }
                M[base + w] = bits;
            }
        }
    }
    __syncthreads();

    if (t < 32) {                        // serial greedy, warp 0; rem in registers
        u32 myrem;
        {
            int lo = lane*32;
            if      (lane >= 16)     myrem = 0xFFFFFFFFu;
            else if (nv >= lo + 32)  myrem = 0u;
            else if (nv <= lo)       myrem = 0xFFFFFFFFu;
            else                     myrem = ~((1u << (nv - lo)) - 1u);
        }
        int kept = 0;
        for (int i = 0; i < nv; ++i) {
            int k = i >> 5;
            u32 wv = __shfl_sync(0xFFFFFFFFu, myrem, k);
            if (!((wv >> (i & 31)) & 1u)) {
                if (lane == 0) KP[kept] = (short)i;
                kept++;
                if (kept >= NMSMAX) break;
                if (lane >= k && lane < 16)
                    myrem |= M[RB(i) - k + lane];
            }
        }
        if (lane == 0) s_kept = kept;
    }
    __syncthreads();
    int kept = s_kept;
    for (int p = t; p < NMSMAX; p += 256) {      // full block: entries + zero tail
        size_t o = (size_t)b*FLAT + c*NMSMAX + p;
        float* e = g_flat + o*6;
        if (p < kept) {
            int j = KP[p];
            float4 bx = B4[j];
            float s = SC[j];
            g_topscore[o] = s;
            e[0] = (float)(c+1);
            e[1] = s;
            e[2] = bx.x; e[3] = bx.y; e[4] = bx.z; e[5] = bx.w;
            atomicAdd(&g_hist[b*NBIN + BKT(__float_as_uint(s))], 1u);
        } else {
            g_topscore[o] = 0.0f;
            e[0]=0.f; e[1]=0.f; e[2]=0.f; e[3]=0.f; e[4]=0.f; e[5]=0.f;
        }
    }
}

// ---------------- kernel 4: pivot + compact + single 512-sort ----------------
// Pivot bucket B1 = fine bucket of the rank-200 score; admit whole bucket
// (tie-exact: intra-bucket order resolved by the full-key sort). Fallback to the
// exact full-scan chunked path if pivot not found (n < 200) or adm > 512.
__global__ void k_topk(float* __restrict__ out) {
    __shared__ u32 hist[NBIN];          // 16 KB
    __shared__ u64 pend[KC + KC/32];    // 4.2 KB
    __shared__ u64 cur[256];
    __shared__ u64 chk[KC];
    __shared__ int s_b1, s_adm, s_pcnt;
    int b = blockIdx.x, t = threadIdx.x, lane = t & 31;
    if (t == 0) { s_b1 = -1; s_adm = 0x7FFFFFFF; s_pcnt = 0; }
    #pragma unroll
    for (int r = 0; r < NBIN/256; ++r) hist[t + r*256] = g_hist[b*NBIN + t + r*256];
    __syncthreads();

    const float* sc = g_topscore + (size_t)b*FLAT;

    if (t < 32) {                       // pivot: rank TOPK from the top
        int cum = 0;
        for (int c = NBIN/32 - 1; c >= 0; --c) {
            u32 h = hist[c*32 + lane];
            if (!__ballot_sync(0xFFFFFFFFu, h != 0u)) continue;
            u32 sfx = h;
            #pragma unroll
            for (int off = 1; off < 32; off <<= 1) {
                u32 v = __shfl_down_sync(0xFFFFFFFFu, sfx, off);
                if (lane + off < 32) sfx += v;
            }
            u32 tot = __shfl_sync(0xFFFFFFFFu, sfx, 0);
            if (cum + (int)tot >= TOPK) {
                bool cond = (cum + (int)sfx) >= TOPK;
                u32 mask = __ballot_sync(0xFFFFFFFFu, cond);
                int L = 31 - __clz(mask);
                u32 sfxL = __shfl_sync(0xFFFFFFFFu, sfx, L);
                if (lane == 0) { s_b1 = c*32 + L; s_adm = cum + (int)sfxL; }
                break;
            }
            cum += (int)tot;
        }
    }
    __syncthreads();
    int B1 = s_b1, adm = s_adm;

    if (B1 >= 0 && adm <= KC) {
        pend[SK(t)] = 0ULL; pend[SK(t+256)] = 0ULL;
        __syncthreads();
        // 4-way pipelined scan over FLAT4 (31*1024), then one exact 256-wide tail
        for (int nb = 0; nb < FLAT4; nb += 1024) {
            float sv[4];
            #pragma unroll
            for (int r = 0; r < 4; ++r) sv[r] = sc[nb + r*256 + t];
            #pragma unroll
            for (int r = 0; r < 4; ++r) {
                int i = nb + r*256 + t;
                float s = sv[r];
                bool pass = (s > 0.0f) && (BKT(__float_as_uint(s)) >= B1);
                u64 key = ((u64)__float_as_uint(s) << 32) | (u64)(0xFFFFFFFFu - (u32)i);
                u32 m = __ballot_sync(0xFFFFFFFFu, pass);
                if (m) {
                    int rank = __popc(m & ((1u << lane) - 1u));
                    u32 posb = 0;
                    if (lane == 0) posb = atomicAdd(&s_pcnt, __popc(m));
                    posb = __shfl_sync(0xFFFFFFFFu, posb, 0);
                    if (pass) pend[SK(posb + rank)] = key;   // <= adm <= 512
                }
            }
        }
        {   // tail: FLAT - FLAT4 = 256 elements exactly
            int i = FLAT4 + t;
            float s = sc[i];
            bool pass = (s > 0.0f) && (BKT(__float_as_uint(s)) >= B1);
            u64 key = ((u64)__float_as_uint(s) << 32) | (u64)(0xFFFFFFFFu - (u32)i);
            u32 m = __ballot_sync(0xFFFFFFFFu, pass);
            if (m) {
                int rank = __popc(m & ((1u << lane) - 1u));
                u32 posb = 0;
                if (lane == 0) posb = atomicAdd(&s_pcnt, __popc(m));
                posb = __shfl_sync(0xFFFFFFFFu, posb, 0);
                if (pass) pend[SK(posb + rank)] = key;
            }
        }
        __syncthreads();
        for (int kk = 2; kk <= KC; kk <<= 1) {
            for (int j = kk >> 1; j > 0; j >>= 1) {
                LAYER_BAR(j);
                int i = ((t & ~(j-1)) << 1) | (t & (j-1));
                int q = i | j;
                bool up = ((i & kk) == 0);
                u64 a = pend[SK(i)], bb = pend[SK(q)];
                if (up ? (a < bb) : (a > bb)) { pend[SK(i)] = bb; pend[SK(q)] = a; }
            }
        }
        __syncthreads();
        for (int idx = t; idx < TOPK*6; idx += 256) {
            int k = idx / 6, r = idx % 6;
            u64 key = pend[SK(k)];
            u32 flat = 0xFFFFFFFFu - (u32)key;
            out[((size_t)b*TOPK + k)*6 + r] = g_flat[((size_t)b*FLAT + flat)*6 + r];
        }
        return;
    }

    // ---- fallback: exact chunked selection over all FLAT slots ----
    cur[t] = 0ULL;
    __syncthreads();
    int nchc = (FLAT + KC - 1)/KC;
    for (int cidx = 0; cidx < nchc; ++cidx) {
        int base = cidx*KC;
        #pragma unroll
        for (int r = 0; r < 2; ++r) {
            int i = t + r*256;
            int g = base + i;
            u64 key = 0ULL;
            if (g < FLAT) {
                float s = sc[g];
                key = ((u64)__float_as_uint(s) << 32) | (u64)(0xFFFFFFFFu - (u32)g);
            }
            chk[i] = key;
        }
        __syncthreads();
        for (int kk = 2; kk <= KC; kk <<= 1) {
            for (int j = kk >> 1; j > 0; j >>= 1) {
                LAYER_BAR(j);
                int i = ((t & ~(j-1)) << 1) | (t & (j-1));
                int p = i | j;
                bool up = ((i & kk) == 0);
                u64 a = chk[i], bb = chk[p];
                if (up ? (a > bb) : (a < bb)) { chk[i] = bb; chk[p] = a; }
            }
        }
        __syncthreads();
        {
            u64 a = cur[t], bb = chk[256 + t];
            cur[t] = (a > bb) ? a : bb;
        }
        for (int j = 128; j > 0; j >>= 1) {
            LAYER_BAR(j);
            if (t < 128) {
                int i = ((t & ~(j-1)) << 1) | (t & (j-1));
                int p = i | j;
                u64 a = cur[i], bb = cur[p];
                if (a < bb) { cur[i] = bb; cur[p] = a; }
            }
        }
        __syncthreads();
    }
    for (int idx = t; idx < TOPK*6; idx += 256) {
        int k = idx / 6, r = idx % 6;
        u64 key = cur[k];
        u32 flat = 0xFFFFFFFFu - (u32)key;
        out[((size_t)b*TOPK + k)*6 + r] = g_flat[((size_t)b*FLAT + flat)*6 + r];
    }
}

// ---------------- launcher ----------------
extern "C" void kernel_launch(void* const* d_in, const int* in_sizes, int n_in,
                              void* d_out, int out_size) {
    const float* y = (const float*)d_in[0];
    float* out = (float*)d_out;

    k_decode<<<dim3((NBOX + TILE_N - 1)/TILE_N, BATCH), 256>>>(y);
    k_select<<<BATCH*NCLS, 256>>>();
    k_nms<<<BATCH*NCLS, 256>>>();
    k_topk<<<BATCH, 256>>>(out);
}

// round 17
// speedup vs baseline: 1.7131x; 1.0951x over previous
#include <cuda_runtime.h>

#define BATCH  32
#define NBOX   8732
#define NBOX4  8192            // 8*1024: 4-way main-loop bound for the select scan
#define DDIM   93
#define NCLS   80
#define KC     512
#define PC     1024            // pending buffer capacity
#define CAP    2048            // fast-path candidate buffer capacity
#define NMSMAX 400
#define TOPK   200
#define FLAT   (NCLS*NMSMAX)   // 32000 (= 125*256)
#define FLAT4  (FLAT & ~1023)  // 31744 = 31*1024
#define CONF_T 0.01f
#define IOU_T  0.45f
#define NBIN   4096
#define MTRI   4352             // triangular bitmap words: sum_i (16 - (i>>5))
#define PREF   0.875f           // prefilter (exact bin boundary 0x3F600000)
#define C_HI   0.45000450f      // conservative band: > uni*C_HI  => IOU > 0.45 surely
#define C_LO   0.44999550f      // < uni*C_LO => IOU <= 0.45 surely; between: exact fdiv

typedef unsigned long long u64;
typedef unsigned int u32;

#define SK(i) ((i) + ((i) >> 5))   // skewed smem index (bank-conflict relief)

// Barrier before a bitonic layer of stride j (prev layer stride 2j).
// Warp w owns elements [64w,64w+64) for strides <=32. Need __syncthreads iff j >= 32.
#define LAYER_BAR(j) do { if ((j) >= 32) __syncthreads(); else __syncwarp(); } while (0)

// triangular row base: row i stores words [i>>5, 16) at M[RB(i) + w - (i>>5)]
__device__ __forceinline__ int RB(int i) {
    int k = i >> 5;
    return 16*i - k*(i - 16*k - 16);
}

// fine monotone bucket over (0.875, 1]: 4096 bins of 2^9 float-bit steps; clamped
__device__ __forceinline__ int BKT(u32 sb) {
    int v = (int)(sb - 0x3F600000u) >> 9;
    return v < 0 ? 0 : (v > (NBIN-1) ? (NBIN-1) : v);
}

// ---------------- static scratch (no allocations allowed) ----------------
__device__ float4 g_boxes[BATCH*NBOX];
__device__ float  g_scoresT[(size_t)BATCH*NCLS*NBOX];
__device__ u64    g_cands[(size_t)BATCH*NCLS*KC];
__device__ __align__(16) float g_flat[(size_t)BATCH*FLAT*6];
__device__ __align__(16) float g_topscore[(size_t)BATCH*FLAT];
__device__ u32    g_hist[BATCH*NBIN];          // 512 KB, zeroed in k_decode

// ---------------- kernel 1: decode boxes + transpose scores (+ zero g_hist) ----------------
#define TILE_N 64
__global__ void k_decode(const float* __restrict__ y) {
    __shared__ float t[TILE_N*DDIM];
    int b  = blockIdx.y;
    int n0 = blockIdx.x * TILE_N;
    // zero g_hist: first 512 linear blocks clear 256 words each (BATCH*NBIN = 131072)
    {
        int linear = blockIdx.y * gridDim.x + blockIdx.x;
        if (linear < (BATCH*NBIN)/256)
            g_hist[linear*256 + threadIdx.x] = 0u;
    }
    int nn = min(TILE_N, NBOX - n0);
    const float* src = y + ((size_t)b*NBOX + n0)*DDIM;
    for (int i = threadIdx.x; i < nn*DDIM; i += blockDim.x) t[i] = src[i];
    __syncthreads();

    if (threadIdx.x < nn) {
        const float* r = t + threadIdx.x*DDIM;
        float aw = r[87], ah = r[88];
        float cx = __fadd_rn(__fmul_rn(__fmul_rn(r[81], r[89]), aw), r[85]);
        float cy = __fadd_rn(__fmul_rn(__fmul_rn(r[82], r[90]), ah), r[86]);
        float w  = __fmul_rn(expf(__fmul_rn(r[83], r[91])), aw);
        float h  = __fmul_rn(expf(__fmul_rn(r[84], r[92])), ah);
        float xmin = __fmul_rn(__fsub_rn(cx, __fmul_rn(0.5f, w)), 512.0f);
        float ymin = __fmul_rn(__fsub_rn(cy, __fmul_rn(0.5f, h)), 512.0f);
        float xmax = __fmul_rn(__fadd_rn(cx, __fmul_rn(0.5f, w)), 512.0f);
        float ymax = __fmul_rn(__fadd_rn(cy, __fmul_rn(0.5f, h)), 512.0f);
        g_boxes[(size_t)b*NBOX + n0 + threadIdx.x] = make_float4(xmin, ymin, xmax, ymax);
    }
    for (int idx = threadIdx.x; idx < NCLS*TILE_N; idx += blockDim.x) {
        int c = idx / TILE_N, i = idx % TILE_N;
        if (i < nn)
            g_scoresT[((size_t)(b*NCLS + c))*NBOX + n0 + i] = t[i*DDIM + 1 + c];
    }
}

// ---------------- kernel 2: top-512 ----------------
__global__ void k_select() {
    __shared__ u64 cur[KC + KC/32];     // 528  (fallback accumulator)
    __shared__ u64 pend[PC + PC/32];    // 1056
    __shared__ u64 buf[CAP + CAP/32];   // 2112
    __shared__ u32 hist[NBIN];          // 16 KB
    __shared__ int s_pcnt, s_admit, s_bcnt;
    __shared__ u64 s_hthr;
    int task = blockIdx.x;
    int t = threadIdx.x;                // 0..255
    int lane = t & 31;
    const float* sc = g_scoresT + (size_t)task*NBOX;

    cur[SK(t)] = 0ULL; cur[SK(t+256)] = 0ULL;
    #pragma unroll
    for (int r = 0; r < 4; ++r) pend[SK(t + r*256)] = 0ULL;
    #pragma unroll
    for (int r = 0; r < NBIN/256; ++r) hist[t + r*256] = 0u;
    if (t == 0) { s_pcnt = 0; s_hthr = 0ULL; s_admit = 0x7FFFFFFF; s_bcnt = 0; }
    __syncthreads();

    // ---- single-read compaction of keys with s > PREF (4-way pipelined) ----
    for (int nb = 0; nb < NBOX4; nb += 1024) {
        float sv[4];
        #pragma unroll
        for (int r = 0; r < 4; ++r) sv[r] = sc[nb + r*256 + t];
        #pragma unroll
        for (int r = 0; r < 4; ++r) {
            int n = nb + r*256 + t;
            float s = sv[r];
            bool pass = (s > PREF);
            u64 key = ((u64)__float_as_uint(s) << 32) | (u64)(0xFFFFFFFFu - (u32)n);
            u32 m = __ballot_sync(0xFFFFFFFFu, pass);
            if (m) {
                int rank = __popc(m & ((1u << lane) - 1u));
                u32 posb = 0;
                if (lane == 0) posb = atomicAdd(&s_bcnt, __popc(m));
                posb = __shfl_sync(0xFFFFFFFFu, posb, 0);
                if (pass) {
                    u32 pos = posb + rank;
                    if (pos < CAP) buf[SK(pos)] = key;
                }
            }
        }
    }
    for (int nb = NBOX4; nb < NBOX; nb += 256) {   // guarded tail: 3 uniform trips
        int n = nb + t;
        u64 key = 0ULL; bool pass = false;
        if (n < NBOX) {
            float s = sc[n];
            if (s > PREF) {
                key = ((u64)__float_as_uint(s) << 32) | (u64)(0xFFFFFFFFu - (u32)n);
                pass = true;
            }
        }
        u32 m = __ballot_sync(0xFFFFFFFFu, pass);
        if (m) {
            int rank = __popc(m & ((1u << lane) - 1u));
            u32 posb = 0;
            if (lane == 0) posb = atomicAdd(&s_bcnt, __popc(m));
            posb = __shfl_sync(0xFFFFFFFFu, posb, 0);
            if (pass) {
                u32 pos = posb + rank;
                if (pos < CAP) buf[SK(pos)] = key;
            }
        }
    }
    __syncthreads();
    int bcnt = s_bcnt;
    bool fast = (bcnt >= KC && bcnt <= CAP);

    if (fast) {
        for (int i = t; i < bcnt; i += 256)
            atomicAdd(&hist[(u32)(buf[SK(i)] >> 51)], 1u);
    } else {
        for (int n = t; n < NBOX; n += 256) {
            float s = sc[n];
            if (s > PREF) atomicAdd(&hist[__float_as_uint(s) >> 19], 1u);
        }
    }
    __syncthreads();
    if (t < 32) {
        int cum = 0;
        for (int c = NBIN/32 - 1; c >= 0; --c) {
            u32 h = hist[c*32 + lane];
            if (!__ballot_sync(0xFFFFFFFFu, h != 0u)) continue;
            u32 sfx = h;
            #pragma unroll
            for (int off = 1; off < 32; off <<= 1) {
                u32 v = __shfl_down_sync(0xFFFFFFFFu, sfx, off);
                if (lane + off < 32) sfx += v;
            }
            u32 tot = __shfl_sync(0xFFFFFFFFu, sfx, 0);
            if (cum + (int)tot >= KC) {
                bool cond = (cum + (int)sfx) >= KC;
                u32 mask = __ballot_sync(0xFFFFFFFFu, cond);
                int L = 31 - __clz(mask);
                u32 B = (u32)(c*32 + L);
                u32 adm = cum + __shfl_sync(0xFFFFFFFFu, sfx, L);
                if (lane == 0) { s_hthr = ((u64)(B << 19)) << 32; s_admit = (int)adm; }
                break;
            }
            cum += (int)tot;
        }
    }
    __syncthreads();
    u64 hthr = s_hthr;
    int admit = s_admit;

    if (fast && admit <= PC) {
        for (int nb = 0; nb < CAP; nb += 256) {
            int i = nb + t;
            u64 key = 0ULL; bool pass = false;
            if (i < bcnt) { key = buf[SK(i)]; pass = key > hthr; }
            u32 m = __ballot_sync(0xFFFFFFFFu, pass);
            int rank = __popc(m & ((1u << lane) - 1u));
            u32 posb = 0;
            if (lane == 0 && m) posb = atomicAdd(&s_pcnt, __popc(m));
            posb = __shfl_sync(0xFFFFFFFFu, posb, 0);
            if (pass) pend[SK(posb + rank)] = key;
        }
        __syncthreads();
        for (int kk = 2; kk <= PC; kk <<= 1) {
            for (int j = kk >> 1; j > 0; j >>= 1) {
                LAYER_BAR(j);
                #pragma unroll
                for (int r = 0; r < 2; ++r) {
                    int pi = t + r*256;
                    int i = ((pi & ~(j-1)) << 1) | (pi & (j-1));
                    int q = i | j;
                    bool up = ((i & kk) == 0);
                    u64 a = pend[SK(i)], bb = pend[SK(q)];
                    if (up ? (a < bb) : (a > bb)) { pend[SK(i)] = bb; pend[SK(q)] = a; }
                }
            }
        }
        __syncthreads();
        g_cands[(size_t)task*KC + t]       = pend[SK(t)];
        g_cands[(size_t)task*KC + t + 256] = pend[SK(t + 256)];
        return;
    }

    // ---- fallback: chunked filtered compaction (exact for any input) ----
    const int nch = (NBOX + KC - 1)/KC;
    for (int cidx = 0; cidx < nch; ++cidx) {
        u64 thr0 = cur[SK(KC-1)];
        u64 thr = (thr0 > hthr) ? thr0 : hthr;
        int base = cidx*KC;
        #pragma unroll
        for (int r = 0; r < 2; ++r) {
            int n = base + t + r*256;
            u64 key = 0ULL;
            if (n < NBOX) {
                float s = sc[n];
                if (s > CONF_T)
                    key = ((u64)__float_as_uint(s) << 32) | (u64)(0xFFFFFFFFu - (u32)n);
            }
            bool pass = key > thr;
            u32 mask = __ballot_sync(0xFFFFFFFFu, pass);
            int rank = __popc(mask & ((1u << lane) - 1u));
            u32 posb = 0;
            if (lane == 0 && mask) posb = atomicAdd(&s_pcnt, __popc(mask));
            posb = __shfl_sync(0xFFFFFFFFu, posb, 0);
            if (pass) {
                u32 pos = posb + rank;
                if (pos < PC) pend[SK(pos)] = key;
            }
        }
        __syncthreads();
        int p = s_pcnt;
        __syncthreads();
        bool last = (cidx == nch - 1);
        bool fl = (admit <= PC) ? (last && p > 0)
                                : ((p > KC) || (last && p > 0));
        if (fl) {
            for (int kk = 2; kk <= PC; kk <<= 1) {
                for (int j = kk >> 1; j > 0; j >>= 1) {
                    LAYER_BAR(j);
                    #pragma unroll
                    for (int r = 0; r < 2; ++r) {
                        int pi = t + r*256;
                        int i = ((pi & ~(j-1)) << 1) | (pi & (j-1));
                        int q = i | j;
                        bool up = ((i & kk) == 0);
                        u64 a = pend[SK(i)], bb = pend[SK(q)];
                        if (up ? (a > bb) : (a < bb)) { pend[SK(i)] = bb; pend[SK(q)] = a; }
                    }
                }
            }
            __syncthreads();
            {
                u64 a = cur[SK(t)],      bb = pend[SK(KC + t)];
                cur[SK(t)] = (a > bb) ? a : bb;
                u64 a2 = cur[SK(t+256)], b2 = pend[SK(KC + t + 256)];
                cur[SK(t+256)] = (a2 > b2) ? a2 : b2;
            }
            for (int j = KC >> 1; j > 0; j >>= 1) {
                LAYER_BAR(j);
                int i = ((t & ~(j-1)) << 1) | (t & (j-1));
                int q = i | j;
                u64 a = cur[SK(i)], bb = cur[SK(q)];
                if (a < bb) { cur[SK(i)] = bb; cur[SK(q)] = a; }
            }
            __syncthreads();
            #pragma unroll
            for (int r = 0; r < 4; ++r) pend[SK(t + r*256)] = 0ULL;
            if (t == 0) s_pcnt = 0;
            __syncthreads();
        }
    }
    g_cands[(size_t)task*KC + t]       = cur[SK(t)];
    g_cands[(size_t)task*KC + t + 256] = cur[SK(t + 256)];
}

// ---------------- kernel 3: bit-matrix greedy NMS ----------------
// Phase 1: reversed-j bit packing ((bits<<1)|hit, one LEA-class op per test
// instead of SHF+LOP); constant realign shift once per partial word. Epilogue
// writes kept rows + zero tail + fine histogram (feeds k_topk).
__global__ void k_nms() {
    __shared__ float4 B4[KC];            // 8 KB
    __shared__ float AR[KC], SC[KC];     // 4 KB
    __shared__ u32 M[MTRI];              // 17408 B
    __shared__ short KP[NMSMAX];
    __shared__ int s_nv, s_kept;
    int task = blockIdx.x;
    int b = task / NCLS, c = task % NCLS;
    int t = threadIdx.x, lane = t & 31;

    if (t == 0) s_nv = KC;
    #pragma unroll
    for (int r = 0; r < MTRI/256; ++r) M[t + r*256] = 0u;
    __syncthreads();

    const u64* cand = g_cands + (size_t)task*KC;
    #pragma unroll
    for (int r = 0; r < 2; ++r) {
        int i = t + r*256;
        u64 key = cand[i];
        u32 hi = (u32)(key >> 32);
        float4 bx = make_float4(0.f,0.f,0.f,0.f);
        if (hi != 0u) {
            bx = g_boxes[(size_t)b*NBOX + (0xFFFFFFFFu - (u32)key)];
        } else {
            atomicMin(&s_nv, i);
        }
        B4[i] = bx;
        AR[i] = __fmul_rn(__fsub_rn(bx.z,bx.x), __fsub_rn(bx.w,bx.y));
        SC[i] = __uint_as_float(hi);
    }
    __syncthreads();
    int nv = s_nv;

    #pragma unroll
    for (int rr = 0; rr < 2; ++rr) {
        int i = rr ? (KC-1-t) : t;
        if (i < nv - 1) {
            float4 bi = B4[i];
            float ia = AR[i];
            int k = i >> 5;
            int base = RB(i) - k;
            int wend = (nv + 31) >> 5;
            for (int w = (i+1) >> 5; w < wend; ++w) {
                u32 bits = 0u;
                int j0 = max(i+1, w << 5);
                int j1 = min(nv, (w+1) << 5);
                for (int j = j1 - 1; j >= j0; --j) {   // reversed: bits=(bits<<1)|hit
                    float4 bj = B4[j];
                    float xx1 = fmaxf(bi.x, bj.x);
                    float yy1 = fmaxf(bi.y, bj.y);
                    float xx2 = fminf(bi.z, bj.z);
                    float yy2 = fminf(bi.w, bj.w);
                    float dw = fmaxf(__fsub_rn(xx2, xx1), 0.0f);
                    float dh = fmaxf(__fsub_rn(yy2, yy1), 0.0f);
                    float inter = __fmul_rn(dw, dh);
                    float uni = __fsub_rn(__fadd_rn(ia, AR[j]), inter);
                    bool hit;
                    if      (inter > __fmul_rn(uni, C_HI)) hit = (uni > 0.0f);
                    else if (inter < __fmul_rn(uni, C_LO)) hit = false;
                    else hit = (uni > 0.0f) && (__fdiv_rn(inter, uni) > IOU_T);
                    bits = (bits << 1) | (u32)hit;
                }
                bits <<= (j0 & 31);                    // realign partial first word
                M[base + w] = bits;
            }
        }
    }
    __syncthreads();

    if (t < 32) {                        // serial greedy, warp 0; rem in registers
        u32 myrem;
        {
            int lo = lane*32;
            if      (lane >= 16)     myrem = 0xFFFFFFFFu;
            else if (nv >= lo + 32)  myrem = 0u;
            else if (nv <= lo)       myrem = 0xFFFFFFFFu;
            else                     myrem = ~((1u << (nv - lo)) - 1u);
        }
        int kept = 0;
        for (int i = 0; i < nv; ++i) {
            int k = i >> 5;
            u32 wv = __shfl_sync(0xFFFFFFFFu, myrem, k);
            if (!((wv >> (i & 31)) & 1u)) {
                if (lane == 0) KP[kept] = (short)i;
                kept++;
                if (kept >= NMSMAX) break;
                if (lane >= k && lane < 16)
                    myrem |= M[RB(i) - k + lane];
            }
        }
        if (lane == 0) s_kept = kept;
    }
    __syncthreads();
    int kept = s_kept;
    for (int p = t; p < NMSMAX; p += 256) {      // full block: entries + zero tail
        size_t o = (size_t)b*FLAT + c*NMSMAX + p;
        float* e = g_flat + o*6;
        if (p < kept) {
            int j = KP[p];
            float4 bx = B4[j];
            float s = SC[j];
            g_topscore[o] = s;
            e[0] = (float)(c+1);
            e[1] = s;
            e[2] = bx.x; e[3] = bx.y; e[4] = bx.z; e[5] = bx.w;
            atomicAdd(&g_hist[b*NBIN + BKT(__float_as_uint(s))], 1u);
        } else {
            g_topscore[o] = 0.0f;
            e[0]=0.f; e[1]=0.f; e[2]=0.f; e[3]=0.f; e[4]=0.f; e[5]=0.f;
        }
    }
}

// ---------------- kernel 4: pivot + compact + single 512-sort ----------------
__global__ void k_topk(float* __restrict__ out) {
    __shared__ u32 hist[NBIN];          // 16 KB
    __shared__ u64 pend[KC + KC/32];    // 4.2 KB
    __shared__ u64 cur[256];
    __shared__ u64 chk[KC];
    __shared__ int s_b1, s_adm, s_pcnt;
    int b = blockIdx.x, t = threadIdx.x, lane = t & 31;
    if (t == 0) { s_b1 = -1; s_adm = 0x7FFFFFFF; s_pcnt = 0; }
    #pragma unroll
    for (int r = 0; r < NBIN/256; ++r) hist[t + r*256] = g_hist[b*NBIN + t + r*256];
    __syncthreads();

    const float* sc = g_topscore + (size_t)b*FLAT;

    if (t < 32) {                       // pivot: rank TOPK from the top
        int cum = 0;
        for (int c = NBIN/32 - 1; c >= 0; --c) {
            u32 h = hist[c*32 + lane];
            if (!__ballot_sync(0xFFFFFFFFu, h != 0u)) continue;
            u32 sfx = h;
            #pragma unroll
            for (int off = 1; off < 32; off <<= 1) {
                u32 v = __shfl_down_sync(0xFFFFFFFFu, sfx, off);
                if (lane + off < 32) sfx += v;
            }
            u32 tot = __shfl_sync(0xFFFFFFFFu, sfx, 0);
            if (cum + (int)tot >= TOPK) {
                bool cond = (cum + (int)sfx) >= TOPK;
                u32 mask = __ballot_sync(0xFFFFFFFFu, cond);
                int L = 31 - __clz(mask);
                u32 sfxL = __shfl_sync(0xFFFFFFFFu, sfx, L);
                if (lane == 0) { s_b1 = c*32 + L; s_adm = cum + (int)sfxL; }
                break;
            }
            cum += (int)tot;
        }
    }
    __syncthreads();
    int B1 = s_b1, adm = s_adm;

    if (B1 >= 0 && adm <= KC) {
        pend[SK(t)] = 0ULL; pend[SK(t+256)] = 0ULL;
        __syncthreads();
        for (int nb = 0; nb < FLAT4; nb += 1024) {
            float sv[4];
            #pragma unroll
            for (int r = 0; r < 4; ++r) sv[r] = sc[nb + r*256 + t];
            #pragma unroll
            for (int r = 0; r < 4; ++r) {
                int i = nb + r*256 + t;
                float s = sv[r];
                bool pass = (s > 0.0f) && (BKT(__float_as_uint(s)) >= B1);
                u64 key = ((u64)__float_as_uint(s) << 32) | (u64)(0xFFFFFFFFu - (u32)i);
                u32 m = __ballot_sync(0xFFFFFFFFu, pass);
                if (m) {
                    int rank = __popc(m & ((1u << lane) - 1u));
                    u32 posb = 0;
                    if (lane == 0) posb = atomicAdd(&s_pcnt, __popc(m));
                    posb = __shfl_sync(0xFFFFFFFFu, posb, 0);
                    if (pass) pend[SK(posb + rank)] = key;
                }
            }
        }
        {   // tail: FLAT - FLAT4 = 256 elements exactly
            int i = FLAT4 + t;
            float s = sc[i];
            bool pass = (s > 0.0f) && (BKT(__float_as_uint(s)) >= B1);
            u64 key = ((u64)__float_as_uint(s) << 32) | (u64)(0xFFFFFFFFu - (u32)i);
            u32 m = __ballot_sync(0xFFFFFFFFu, pass);
            if (m) {
                int rank = __popc(m & ((1u << lane) - 1u));
                u32 posb = 0;
                if (lane == 0) posb = atomicAdd(&s_pcnt, __popc(m));
                posb = __shfl_sync(0xFFFFFFFFu, posb, 0);
                if (pass) pend[SK(posb + rank)] = key;
            }
        }
        __syncthreads();
        for (int kk = 2; kk <= KC; kk <<= 1) {
            for (int j = kk >> 1; j > 0; j >>= 1) {
                LAYER_BAR(j);
                int i = ((t & ~(j-1)) << 1) | (t & (j-1));
                int q = i | j;
                bool up = ((i & kk) == 0);
                u64 a = pend[SK(i)], bb = pend[SK(q)];
                if (up ? (a < bb) : (a > bb)) { pend[SK(i)] = bb; pend[SK(q)] = a; }
            }
        }
        __syncthreads();
        for (int idx = t; idx < TOPK*6; idx += 256) {
            int k = idx / 6, r = idx % 6;
            u64 key = pend[SK(k)];
            u32 flat = 0xFFFFFFFFu - (u32)key;
            out[((size_t)b*TOPK + k)*6 + r] = g_flat[((size_t)b*FLAT + flat)*6 + r];
        }
        return;
    }

    // ---- fallback: exact chunked selection over all FLAT slots ----
    cur[t] = 0ULL;
    __syncthreads();
    int nchc = (FLAT + KC - 1)/KC;
    for (int cidx = 0; cidx < nchc; ++cidx) {
        int base = cidx*KC;
        #pragma unroll
        for (int r = 0; r < 2; ++r) {
            int i = t + r*256;
            int g = base + i;
            u64 key = 0ULL;
            if (g < FLAT) {
                float s = sc[g];
                key = ((u64)__float_as_uint(s) << 32) | (u64)(0xFFFFFFFFu - (u32)g);
            }
            chk[i] = key;
        }
        __syncthreads();
        for (int kk = 2; kk <= KC; kk <<= 1) {
            for (int j = kk >> 1; j > 0; j >>= 1) {
                LAYER_BAR(j);
                int i = ((t & ~(j-1)) << 1) | (t & (j-1));
                int p = i | j;
                bool up = ((i & kk) == 0);
                u64 a = chk[i], bb = chk[p];
                if (up ? (a > bb) : (a < bb)) { chk[i] = bb; chk[p] = a; }
            }
        }
        __syncthreads();
        {
            u64 a = cur[t], bb = chk[256 + t];
            cur[t] = (a > bb) ? a : bb;
        }
        for (int j = 128; j > 0; j >>= 1) {
            LAYER_BAR(j);
            if (t < 128) {
                int i = ((t & ~(j-1)) << 1) | (t & (j-1));
                int p = i | j;
                u64 a = cur[i], bb = cur[p];
                if (a < bb) { cur[i] = bb; cur[p] = a; }
            }
        }
        __syncthreads();
    }
    for (int idx = t; idx < TOPK*6; idx += 256) {
        int k = idx / 6, r = idx % 6;
        u64 key = cur[k];
        u32 flat = 0xFFFFFFFFu - (u32)key;
        out[((size_t)b*TOPK + k)*6 + r] = g_flat[((size_t)b*FLAT + flat)*6 + r];
    }
}

// ---------------- launcher ----------------
extern "C" void kernel_launch(void* const* d_in, const int* in_sizes, int n_in,
                              void* d_out, int out_size) {
    const float* y = (const float*)d_in[0];
    float* out = (float*)d_out;

    k_decode<<<dim3((NBOX + TILE_N - 1)/TILE_N, BATCH), 256>>>(y);
    k_select<<<BATCH*NCLS, 256>>>();
    k_nms<<<BATCH*NCLS, 256>>>();
    k_topk<<<BATCH, 256>>>(out);
}